// round 7
// baseline (speedup 1.0000x reference)
#include <cuda_runtime.h>
#include <stdint.h>

#define Lq     2048
#define EMB    1024
#define NHEAD  16
#define HD     64

// Scratch (allocation-free rule: device globals)
__device__ float g_Q[Lq * EMB];
__device__ float g_K[Lq * EMB];
__device__ float g_V[Lq * EMB];
__device__ float g_A[Lq * EMB];

__device__ __forceinline__ float to_tf32(float x) {
    float r; asm("cvt.rna.tf32.f32 %0, %1;" : "=f"(r) : "f"(x)); return r;
}

// m16n8k8 tf32 HMMA, D (+)= A*B, row.col
__device__ __forceinline__ void mma_tf32(float d[4], const float a0, const float a1,
                                         const float a2, const float a3,
                                         const float b0, const float b1) {
    asm volatile(
        "mma.sync.aligned.m16n8k8.row.col.f32.tf32.tf32.f32 "
        "{%0,%1,%2,%3}, {%4,%5,%6,%7}, {%8,%9}, {%0,%1,%2,%3};\n"
        : "+f"(d[0]), "+f"(d[1]), "+f"(d[2]), "+f"(d[3])
        : "r"(__float_as_uint(a0)), "r"(__float_as_uint(a1)),
          "r"(__float_as_uint(a2)), "r"(__float_as_uint(a3)),
          "r"(__float_as_uint(b0)), "r"(__float_as_uint(b1)));
}

// ===========================================================================
// Warp-MMA tf32 NT GEMM, 3xTF32 split, register-prefetch double buffering.
// CTA tile 128x128, 8 warps (2m x 4n), warp tile 64x32, K-chunk 16.
// ===========================================================================
__global__ __launch_bounds__(256, 2)
void gemm_mma_kernel(const float* __restrict__ A, const float* __restrict__ B,
                     float* __restrict__ C)
{
    __shared__ float As_hi[128][20], As_lo[128][20];
    __shared__ float Bs_hi[128][20], Bs_lo[128][20];

    const int tid  = threadIdx.x;
    const int lane = tid & 31;
    const int wid  = tid >> 5;
    const int g    = lane >> 2;
    const int t4   = lane & 3;
    const int wm   = (wid & 1) * 64;
    const int wn   = (wid >> 1) * 32;

    const int bm = blockIdx.y * 128;
    const int bn = blockIdx.x * 128;

    // loader coordinates (function of tid only)
    const int r0  = tid >> 2,        c40 = (tid & 3) * 4;          // j = 0
    const int r1  = (256 + tid) >> 2, c41 = ((256 + tid) & 3) * 4; // j = 1
    const float* a0p = A + (size_t)(bm + r0) * EMB + c40;
    const float* b0p = B + (size_t)(bn + r0) * EMB + c40;
    const float* a1p = A + (size_t)(bm + r1) * EMB + c41;
    const float* b1p = B + (size_t)(bn + r1) * EMB + c41;

    float d[4][4][4];
    #pragma unroll
    for (int i = 0; i < 4; ++i)
        #pragma unroll
        for (int j = 0; j < 4; ++j)
            #pragma unroll
            for (int r = 0; r < 4; ++r) d[i][j][r] = 0.f;

    // prefetch chunk 0
    float4 pa0 = *(const float4*)a0p, pb0 = *(const float4*)b0p;
    float4 pa1 = *(const float4*)a1p, pb1 = *(const float4*)b1p;

    for (int c = 0; c < EMB / 16; ++c) {
        __syncthreads();   // previous compute done with buffer

        // split & store current chunk
        {
            float4 ah, al, bh, bl;
            ah = make_float4(to_tf32(pa0.x), to_tf32(pa0.y), to_tf32(pa0.z), to_tf32(pa0.w));
            al = make_float4(to_tf32(pa0.x - ah.x), to_tf32(pa0.y - ah.y),
                             to_tf32(pa0.z - ah.z), to_tf32(pa0.w - ah.w));
            bh = make_float4(to_tf32(pb0.x), to_tf32(pb0.y), to_tf32(pb0.z), to_tf32(pb0.w));
            bl = make_float4(to_tf32(pb0.x - bh.x), to_tf32(pb0.y - bh.y),
                             to_tf32(pb0.z - bh.z), to_tf32(pb0.w - bh.w));
            *(float4*)&As_hi[r0][c40] = ah; *(float4*)&As_lo[r0][c40] = al;
            *(float4*)&Bs_hi[r0][c40] = bh; *(float4*)&Bs_lo[r0][c40] = bl;

            ah = make_float4(to_tf32(pa1.x), to_tf32(pa1.y), to_tf32(pa1.z), to_tf32(pa1.w));
            al = make_float4(to_tf32(pa1.x - ah.x), to_tf32(pa1.y - ah.y),
                             to_tf32(pa1.z - ah.z), to_tf32(pa1.w - ah.w));
            bh = make_float4(to_tf32(pb1.x), to_tf32(pb1.y), to_tf32(pb1.z), to_tf32(pb1.w));
            bl = make_float4(to_tf32(pb1.x - bh.x), to_tf32(pb1.y - bh.y),
                             to_tf32(pb1.z - bh.z), to_tf32(pb1.w - bh.w));
            *(float4*)&As_hi[r1][c41] = ah; *(float4*)&As_lo[r1][c41] = al;
            *(float4*)&Bs_hi[r1][c41] = bh; *(float4*)&Bs_lo[r1][c41] = bl;
        }
        // prefetch next chunk (latency hides under MMAs below)
        if (c + 1 < EMB / 16) {
            pa0 = *(const float4*)(a0p + (c + 1) * 16);
            pb0 = *(const float4*)(b0p + (c + 1) * 16);
            pa1 = *(const float4*)(a1p + (c + 1) * 16);
            pb1 = *(const float4*)(b1p + (c + 1) * 16);
        }
        __syncthreads();

        #pragma unroll
        for (int ks = 0; ks < 2; ++ks) {
            const int k0 = ks * 8 + t4;
            float bhi[4][2], blo[4][2];
            #pragma unroll
            for (int ni = 0; ni < 4; ++ni) {
                int n = wn + ni * 8 + g;
                bhi[ni][0] = Bs_hi[n][k0];     bhi[ni][1] = Bs_hi[n][k0 + 4];
                blo[ni][0] = Bs_lo[n][k0];     blo[ni][1] = Bs_lo[n][k0 + 4];
            }
            #pragma unroll
            for (int mi = 0; mi < 4; ++mi) {
                int m = wm + mi * 16 + g;
                float ah0 = As_hi[m][k0],     ah1 = As_hi[m + 8][k0];
                float ah2 = As_hi[m][k0 + 4], ah3 = As_hi[m + 8][k0 + 4];
                float al0 = As_lo[m][k0],     al1 = As_lo[m + 8][k0];
                float al2 = As_lo[m][k0 + 4], al3 = As_lo[m + 8][k0 + 4];
                #pragma unroll
                for (int ni = 0; ni < 4; ++ni) {
                    mma_tf32(d[mi][ni], ah0, ah1, ah2, ah3, bhi[ni][0], bhi[ni][1]);
                    mma_tf32(d[mi][ni], ah0, ah1, ah2, ah3, blo[ni][0], blo[ni][1]);
                    mma_tf32(d[mi][ni], al0, al1, al2, al3, bhi[ni][0], bhi[ni][1]);
                }
            }
        }
    }

    #pragma unroll
    for (int mi = 0; mi < 4; ++mi) {
        int m = bm + wm + mi * 16 + g;
        #pragma unroll
        for (int ni = 0; ni < 4; ++ni) {
            int n = bn + wn + ni * 8 + 2 * t4;
            *(float2*)(C + (size_t)m * EMB + n)       = make_float2(d[mi][ni][0], d[mi][ni][1]);
            *(float2*)(C + (size_t)(m + 8) * EMB + n) = make_float2(d[mi][ni][2], d[mi][ni][3]);
        }
    }
}

// ===========================================================================
// Tensor-core flash attention, frag-packed smem.
// Kf[ks][ni][lane] : float4 {khi(t4), khi(t4+4), klo(t4), klo(t4+4)}
//   -> one LDS.128 per (ks,ni) feeds all 3 QK^T MMAs, lane-sequential.
// Vf[ki][ni][lane] : float2 {v(key=8ki+t4, n=8ni+g), v(key=8ki+t4+4, ...)}
//   -> one LDS.64 per (ki,ni), lane-sequential.
// ===========================================================================
#define OFF_KF 0
#define OFF_VF 32768
#define OFF_MK 49152
#define ATTN_SMEM 50176

__global__ __launch_bounds__(256, 1)
void attn_mma_kernel(const float* __restrict__ Q, const float* __restrict__ Kg,
                     const float* __restrict__ Vg, const int* __restrict__ mask,
                     float* __restrict__ O)
{
    extern __shared__ char smem[];
    float4*   Kf  = (float4*)(smem + OFF_KF);    // [8ks][8ni][32] float4
    float2*   Vf  = (float2*)(smem + OFF_VF);    // [8ki][8ni][32] float2
    float*    Vff = (float*)(smem + OFF_VF);
    uint32_t* Mk  = (uint32_t*)(smem + OFF_MK);

    const int tid  = threadIdx.x;
    const int lane = tid & 31;
    const int wid  = tid >> 5;
    const int g    = lane >> 2;
    const int t4   = lane & 3;
    const int h    = blockIdx.y;
    const int qb   = blockIdx.x;
    const int hb   = h * HD;
    const int row0 = qb * 128 + wid * 16;

    // ---- Q fragments: scaled by 1/8, split hi/lo, resident all kernel ----
    float qh[8][4], ql[8][4];
    #pragma unroll
    for (int ks = 0; ks < 8; ++ks) {
        int d0 = hb + 8 * ks + t4;
        float v0 = Q[(size_t)(row0 + g)     * EMB + d0]     * 0.125f;
        float v1 = Q[(size_t)(row0 + g + 8) * EMB + d0]     * 0.125f;
        float v2 = Q[(size_t)(row0 + g)     * EMB + d0 + 4] * 0.125f;
        float v3 = Q[(size_t)(row0 + g + 8) * EMB + d0 + 4] * 0.125f;
        qh[ks][0] = to_tf32(v0); ql[ks][0] = to_tf32(v0 - qh[ks][0]);
        qh[ks][1] = to_tf32(v1); ql[ks][1] = to_tf32(v1 - qh[ks][1]);
        qh[ks][2] = to_tf32(v2); ql[ks][2] = to_tf32(v2 - qh[ks][2]);
        qh[ks][3] = to_tf32(v3); ql[ks][3] = to_tf32(v3 - qh[ks][3]);
    }

    float o[8][4];
    #pragma unroll
    for (int ni = 0; ni < 8; ++ni)
        #pragma unroll
        for (int r = 0; r < 4; ++r) o[ni][r] = 0.f;
    float m0 = -1.0e30f, m1 = -1.0e30f;
    float l0 = 0.f, l1 = 0.f;

    // staging coordinates
    const int key  = tid >> 2;        // 0..63 (this thread's key row)
    const int qq   = tid & 3;         // which 16-dim segment
    const int kni  = key >> 3;        // writer's ni for K
    const int kg   = key & 7;         // writer's g  for K
    const int vki  = key >> 3;        // writer's ki for V
    const int vt4  = key & 3;
    const int vhalf = (key >> 2) & 1;
    const int mrow = tid >> 1;
    const int mhf  = tid & 1;

    for (int kt = 0; kt < Lq / 64; ++kt) {
        // ================= staging =================
        {
            const float* ksrc = Kg + (size_t)(kt * 64 + key) * EMB + hb + qq * 16;
            float4 x0 = *(const float4*)(ksrc);
            float4 x1 = *(const float4*)(ksrc + 4);
            float4 x2 = *(const float4*)(ksrc + 8);
            float4 x3 = *(const float4*)(ksrc + 12);
            float xv[16] = {x0.x,x0.y,x0.z,x0.w, x1.x,x1.y,x1.z,x1.w,
                            x2.x,x2.y,x2.z,x2.w, x3.x,x3.y,x3.z,x3.w};
            #pragma unroll
            for (int kk = 0; kk < 2; ++kk) {
                int ks = 2 * qq + kk;
                #pragma unroll
                for (int tt = 0; tt < 4; ++tt) {
                    float v0 = xv[kk * 8 + tt], v1 = xv[kk * 8 + tt + 4];
                    float h0 = to_tf32(v0), h1 = to_tf32(v1);
                    float l0v = to_tf32(v0 - h0), l1v = to_tf32(v1 - h1);
                    Kf[(ks * 8 + kni) * 32 + kg * 4 + tt] = make_float4(h0, h1, l0v, l1v);
                }
            }

            const float* vsrc = Vg + (size_t)(kt * 64 + key) * EMB + hb + qq * 16;
            float4 y0 = *(const float4*)(vsrc);
            float4 y1 = *(const float4*)(vsrc + 4);
            float4 y2 = *(const float4*)(vsrc + 8);
            float4 y3 = *(const float4*)(vsrc + 12);
            float yv[16] = {y0.x,y0.y,y0.z,y0.w, y1.x,y1.y,y1.z,y1.w,
                            y2.x,y2.y,y2.z,y2.w, y3.x,y3.y,y3.z,y3.w};
            #pragma unroll
            for (int i = 0; i < 16; ++i) {
                int dd = qq * 16 + i;
                int ni = dd >> 3, gg = dd & 7;
                Vff[((vki * 8 + ni) * 32 + gg * 4 + vt4) * 2 + vhalf] = to_tf32(yv[i]);
            }

            const int* mb = mask + (size_t)h * Lq * Lq +
                            (size_t)(qb * 128 + mrow) * Lq + kt * 64 + mhf * 32;
            uint32_t bits = 0;
            #pragma unroll
            for (int i = 0; i < 8; ++i) {
                int4 mv = *(const int4*)(mb + i * 4);
                bits |= (uint32_t)(mv.x != 0) << (i * 4 + 0);
                bits |= (uint32_t)(mv.y != 0) << (i * 4 + 1);
                bits |= (uint32_t)(mv.z != 0) << (i * 4 + 2);
                bits |= (uint32_t)(mv.w != 0) << (i * 4 + 3);
            }
            Mk[mrow * 2 + mhf] = bits;
        }
        __syncthreads();

        // ================= S = Q K^T (3xTF32) =================
        float s[8][4];
        #pragma unroll
        for (int ni = 0; ni < 8; ++ni)
            #pragma unroll
            for (int r = 0; r < 4; ++r) s[ni][r] = 0.f;

        #pragma unroll
        for (int ks = 0; ks < 8; ++ks) {
            #pragma unroll
            for (int ni = 0; ni < 8; ++ni) {
                float4 f = Kf[(ks * 8 + ni) * 32 + lane];
                mma_tf32(s[ni], qh[ks][0], qh[ks][1], qh[ks][2], qh[ks][3], f.x, f.y);
                mma_tf32(s[ni], qh[ks][0], qh[ks][1], qh[ks][2], qh[ks][3], f.z, f.w);
                mma_tf32(s[ni], ql[ks][0], ql[ks][1], ql[ks][2], ql[ks][3], f.x, f.y);
            }
        }

        // ================= masked online softmax =================
        const int rbase = wid * 16 + g;
        uint32_t w0lo = Mk[rbase * 2],        w0hi = Mk[rbase * 2 + 1];
        uint32_t w1lo = Mk[(rbase + 8) * 2],  w1hi = Mk[(rbase + 8) * 2 + 1];

        float tm0 = -1.0e30f, tm1 = -1.0e30f;
        #pragma unroll
        for (int ni = 0; ni < 8; ++ni) {
            uint32_t wr0 = (ni < 4) ? w0lo : w0hi;
            uint32_t wr1 = (ni < 4) ? w1lo : w1hi;
            int b = 8 * (ni & 3) + 2 * t4;
            tm0 = fmaxf(tm0, ((wr0 >> b) & 1u)       ? -1.0e30f : s[ni][0]);
            tm0 = fmaxf(tm0, ((wr0 >> (b + 1)) & 1u) ? -1.0e30f : s[ni][1]);
            tm1 = fmaxf(tm1, ((wr1 >> b) & 1u)       ? -1.0e30f : s[ni][2]);
            tm1 = fmaxf(tm1, ((wr1 >> (b + 1)) & 1u) ? -1.0e30f : s[ni][3]);
        }
        tm0 = fmaxf(tm0, __shfl_xor_sync(0xffffffffu, tm0, 1));
        tm0 = fmaxf(tm0, __shfl_xor_sync(0xffffffffu, tm0, 2));
        tm1 = fmaxf(tm1, __shfl_xor_sync(0xffffffffu, tm1, 1));
        tm1 = fmaxf(tm1, __shfl_xor_sync(0xffffffffu, tm1, 2));

        float mn0 = fmaxf(m0, tm0), mn1 = fmaxf(m1, tm1);
        float c0 = __expf(m0 - mn0), c1 = __expf(m1 - mn1);
        m0 = mn0; m1 = mn1;

        float rs0 = 0.f, rs1 = 0.f;
        #pragma unroll
        for (int ni = 0; ni < 8; ++ni) {
            uint32_t wr0 = (ni < 4) ? w0lo : w0hi;
            uint32_t wr1 = (ni < 4) ? w1lo : w1hi;
            int b = 8 * (ni & 3) + 2 * t4;
            float p0 = ((wr0 >> b) & 1u)       ? 0.f : __expf(s[ni][0] - mn0);
            float p1 = ((wr0 >> (b + 1)) & 1u) ? 0.f : __expf(s[ni][1] - mn0);
            float p2 = ((wr1 >> b) & 1u)       ? 0.f : __expf(s[ni][2] - mn1);
            float p3 = ((wr1 >> (b + 1)) & 1u) ? 0.f : __expf(s[ni][3] - mn1);
            s[ni][0] = p0; s[ni][1] = p1; s[ni][2] = p2; s[ni][3] = p3;
            rs0 += p0 + p1; rs1 += p2 + p3;
        }
        rs0 += __shfl_xor_sync(0xffffffffu, rs0, 1);
        rs0 += __shfl_xor_sync(0xffffffffu, rs0, 2);
        rs1 += __shfl_xor_sync(0xffffffffu, rs1, 1);
        rs1 += __shfl_xor_sync(0xffffffffu, rs1, 2);
        l0 = l0 * c0 + rs0;
        l1 = l1 * c1 + rs1;

        #pragma unroll
        for (int ni = 0; ni < 8; ++ni) {
            o[ni][0] *= c0; o[ni][1] *= c0;
            o[ni][2] *= c1; o[ni][3] *= c1;
        }

        // ================= O += P V (tf32) =================
        const int srcA = g * 4 + (t4 >> 1);
        const int srcB = srcA + 2;
        const int par  = t4 & 1;
        #pragma unroll
        for (int ki = 0; ki < 8; ++ki) {
            float e0 = __shfl_sync(0xffffffffu, s[ki][0], srcA);
            float o0 = __shfl_sync(0xffffffffu, s[ki][1], srcA);
            float e2 = __shfl_sync(0xffffffffu, s[ki][0], srcB);
            float o2 = __shfl_sync(0xffffffffu, s[ki][1], srcB);
            float e1 = __shfl_sync(0xffffffffu, s[ki][2], srcA);
            float o1 = __shfl_sync(0xffffffffu, s[ki][3], srcA);
            float e3 = __shfl_sync(0xffffffffu, s[ki][2], srcB);
            float o3 = __shfl_sync(0xffffffffu, s[ki][3], srcB);
            float a0 = to_tf32(par ? o0 : e0);
            float a1 = to_tf32(par ? o1 : e1);
            float a2 = to_tf32(par ? o2 : e2);
            float a3 = to_tf32(par ? o3 : e3);
            #pragma unroll
            for (int ni = 0; ni < 8; ++ni) {
                float2 v = Vf[(ki * 8 + ni) * 32 + lane];
                mma_tf32(o[ni], a0, a1, a2, a3, v.x, v.y);
            }
        }
        __syncthreads();
    }

    // ================= epilogue =================
    float inv0 = (l0 > 0.f) ? (1.f / l0) : 0.f;
    float inv1 = (l1 > 0.f) ? (1.f / l1) : 0.f;
    #pragma unroll
    for (int ni = 0; ni < 8; ++ni) {
        int col = hb + 8 * ni + 2 * t4;
        *(float2*)(O + (size_t)(row0 + g)     * EMB + col) =
            make_float2(o[ni][0] * inv0, o[ni][1] * inv0);
        *(float2*)(O + (size_t)(row0 + g + 8) * EMB + col) =
            make_float2(o[ni][2] * inv1, o[ni][3] * inv1);
    }
}

// ---------------------------------------------------------------------------
extern "C" void kernel_launch(void* const* d_in, const int* in_sizes, int n_in,
                              void* d_out, int out_size)
{
    const float* q    = (const float*)d_in[0];
    const float* k    = (const float*)d_in[1];
    const float* v    = (const float*)d_in[2];
    const int*   mask = (const int*)d_in[3];
    const float* Wq   = (const float*)d_in[4];
    const float* Wk   = (const float*)d_in[5];
    const float* Wv   = (const float*)d_in[6];
    const float* Wo   = (const float*)d_in[7];
    float*       out  = (float*)d_out;

    float *gQ, *gK, *gV, *gA;
    cudaGetSymbolAddress((void**)&gQ, g_Q);
    cudaGetSymbolAddress((void**)&gK, g_K);
    cudaGetSymbolAddress((void**)&gV, g_V);
    cudaGetSymbolAddress((void**)&gA, g_A);

    cudaFuncSetAttribute(attn_mma_kernel,
                         cudaFuncAttributeMaxDynamicSharedMemorySize, ATTN_SMEM);

    dim3 ggrid(EMB / 128, Lq / 128);   // (8, 16)

    gemm_mma_kernel<<<ggrid, 256>>>(q, Wq, gQ);
    gemm_mma_kernel<<<ggrid, 256>>>(k, Wk, gK);
    gemm_mma_kernel<<<ggrid, 256>>>(v, Wv, gV);

    dim3 agrid(Lq / 128, NHEAD);       // (16, 16)
    attn_mma_kernel<<<agrid, 256, ATTN_SMEM>>>(gQ, gK, gV, mask, gA);

    gemm_mma_kernel<<<ggrid, 256>>>(gA, Wo, out);
}